// round 11
// baseline (speedup 1.0000x reference)
#include <cuda_runtime.h>

#define N_NODES 100000
#define N_EDGES 1600000
#define NB      1024
#define IN_F    32
#define H_F     64
#define SCAN_NBLK ((N_NODES + 255) / 256)   // 391

// ---------------- scratch (device globals; no allocations allowed) ----------
__device__ int   g_deg [N_NODES];
__device__ int   g_off [N_NODES];
__device__ int   g_cur [N_NODES];
__device__ int   g_csr [N_EDGES];           // src ids grouped by dst
__device__ int   g_bsum[SCAN_NBLK];
__device__ int   g_boff[SCAN_NBLK];
__device__ __align__(256) float g_agg1[N_NODES * IN_F];  // 12.8 MB
__device__ __align__(256) float g_agg2[N_NODES * H_F];   // 25.6 MB
__device__ __align__(256) float g_h1  [N_NODES * H_F];   // 25.6 MB
__device__ __align__(256) float g_sum1[NB * H_F];
__device__ __align__(256) float g_sum2[NB * H_F];
__device__ __align__(256) float g_cnt [NB];

__device__ __forceinline__ void red_add_v4(float* addr, float4 v) {
    asm volatile("red.global.add.v4.f32 [%0], {%1, %2, %3, %4};"
                 :: "l"(addr), "f"(v.x), "f"(v.y), "f"(v.z), "f"(v.w)
                 : "memory");
}
__device__ __forceinline__ float4 relu4(float4 a) {
    return make_float4(fmaxf(a.x, 0.f), fmaxf(a.y, 0.f),
                       fmaxf(a.z, 0.f), fmaxf(a.w, 0.f));
}

// ---------------- zero: deg + pools ------------------------------------------
__global__ void zero_kernel() {
    int gid = blockIdx.x * blockDim.x + threadIdx.x;
    if (gid < N_NODES) g_deg[gid] = 0;
    float4 z = make_float4(0.f, 0.f, 0.f, 0.f);
    if (gid < NB * H_F / 4) {
        reinterpret_cast<float4*>(g_sum1)[gid] = z;
        reinterpret_cast<float4*>(g_sum2)[gid] = z;
    }
    if (gid < NB / 4)
        reinterpret_cast<float4*>(g_cnt)[gid] = z;
}

// ---------------- CSR build (validated R6/R9) --------------------------------
__global__ void deg_kernel(const int* __restrict__ dst) {
    int e = blockIdx.x * blockDim.x + threadIdx.x;
    if (e < N_EDGES) atomicAdd(&g_deg[__ldg(dst + e)], 1);
}

__global__ void scan1_kernel() {
    __shared__ int s[256];
    int n = blockIdx.x * 256 + threadIdx.x;
    s[threadIdx.x] = (n < N_NODES) ? g_deg[n] : 0;
    __syncthreads();
    for (int o = 128; o; o >>= 1) {
        if (threadIdx.x < o) s[threadIdx.x] += s[threadIdx.x + o];
        __syncthreads();
    }
    if (threadIdx.x == 0) g_bsum[blockIdx.x] = s[0];
}

__global__ void scan2_kernel() {          // 1 block, 512 threads
    __shared__ int s[512];
    int t = threadIdx.x;
    int v = (t < SCAN_NBLK) ? g_bsum[t] : 0;
    s[t] = v;
    __syncthreads();
    for (int o = 1; o < 512; o <<= 1) {
        int u = (t >= o) ? s[t - o] : 0;
        __syncthreads();
        s[t] += u;
        __syncthreads();
    }
    if (t < SCAN_NBLK) g_boff[t] = s[t] - v;   // exclusive
}

__global__ void scan3_kernel() {
    __shared__ int s[256];
    int t = threadIdx.x;
    int n = blockIdx.x * 256 + t;
    int v = (n < N_NODES) ? g_deg[n] : 0;
    s[t] = v;
    __syncthreads();
    for (int o = 1; o < 256; o <<= 1) {
        int u = (t >= o) ? s[t - o] : 0;
        __syncthreads();
        s[t] += u;
        __syncthreads();
    }
    if (n < N_NODES) {
        int off = g_boff[blockIdx.x] + s[t] - v;
        g_off[n] = off;
        g_cur[n] = off;
    }
}

__global__ void fill_kernel(const int* __restrict__ src,
                            const int* __restrict__ dst) {
    int e = blockIdx.x * blockDim.x + threadIdx.x;
    if (e >= N_EDGES) return;
    int d = __ldg(dst + e);
    int pos = atomicAdd(&g_cur[d], 1);
    g_csr[pos] = __ldg(src + e);
}

// ---------------- gather 1: warp/node, coalesced idx + shfl broadcast --------
__global__ __launch_bounds__(256)
void gather1_kernel(const float* __restrict__ feat) {
    int n = (blockIdx.x * 256 + threadIdx.x) >> 5;
    int lane = threadIdx.x & 31;
    if (n >= N_NODES) return;
    int st = __ldg(&g_off[n]);
    int dg = __ldg(&g_deg[n]);
    float acc = 0.f;
    for (int base = 0; base < dg; base += 32) {
        int rem = dg - base;
        int myidx = (lane < rem) ? __ldg(g_csr + st + base + lane) : 0;
        int m = rem < 32 ? rem : 32;
#pragma unroll 4
        for (int q = 0; q < m; q++) {
            int s = __shfl_sync(0xffffffffu, myidx, q);
            acc += __ldg(feat + (size_t)s * IN_F + lane);
        }
    }
    g_agg1[(size_t)n * IN_F + lane] = acc;
}

// ---------------- gather 2: warp/node, lane = float2, shfl-broadcast idx -----
__global__ __launch_bounds__(256)
void gather2_kernel() {
    int n = (blockIdx.x * 256 + threadIdx.x) >> 5;
    int lane = threadIdx.x & 31;
    if (n >= N_NODES) return;
    int st = __ldg(&g_off[n]);
    int dg = __ldg(&g_deg[n]);
    const float2* h1v = reinterpret_cast<const float2*>(g_h1);
    float2 acc = make_float2(0.f, 0.f);
    for (int base = 0; base < dg; base += 32) {
        int rem = dg - base;
        int myidx = (lane < rem) ? __ldg(g_csr + st + base + lane) : 0;
        int m = rem < 32 ? rem : 32;
#pragma unroll 4
        for (int q = 0; q < m; q++) {
            int s = __shfl_sync(0xffffffffu, myidx, q);
            float2 f = h1v[(size_t)s * 32 + lane];
            acc.x += f.x; acc.y += f.y;
        }
    }
    reinterpret_cast<float2*>(g_agg2)[(size_t)n * 32 + lane] = acc;
}

// ============================================================================
// node MLP 1: x(32) = in_feat + agg1 -> relu(W1 64) -> relu(W2 64)
// writes h1, pools sum1, counts.
// ============================================================================
__global__ __launch_bounds__(128)
void mlp1_kernel(const float* __restrict__ in_feat,
                 const float* __restrict__ w1, const float* __restrict__ b1,
                 const float* __restrict__ w2, const float* __restrict__ b2,
                 const int* __restrict__ gids) {
    __shared__ float4 sx[128 * 8];    // 16 KB
    __shared__ float4 sw[64 * 16];    // 16 KB
    const int tid   = threadIdx.x;
    const int nbase = blockIdx.x * 128;

    for (int idx = tid; idx < 128 * 8; idx += 128) {
        int row = idx >> 3, c = idx & 7;
        int node = nbase + row;
        float4 v = make_float4(0.f, 0.f, 0.f, 0.f);
        if (node < N_NODES) {
            float4 a = __ldg(reinterpret_cast<const float4*>(in_feat) + (size_t)node * 8 + c);
            float4 b = *(reinterpret_cast<const float4*>(g_agg1) + (size_t)node * 8 + c);
            v = make_float4(a.x + b.x, a.y + b.y, a.z + b.z, a.w + b.w);
        }
        sx[row * 8 + (c ^ (row & 7))] = v;
    }
    for (int idx = tid; idx < 512; idx += 128)
        sw[idx] = __ldg(reinterpret_cast<const float4*>(w1) + idx);
    __syncthreads();

    float4 t4[16];
    const int xb = tid * 8, k1 = tid & 7;
    const float4* b1v = reinterpret_cast<const float4*>(b1);
#pragma unroll
    for (int jg = 0; jg < 16; jg++) {
        float4 acc = __ldg(b1v + jg);
#pragma unroll
        for (int ic = 0; ic < 8; ic++) {
            float4 xv = sx[xb + (ic ^ k1)];
            float4 wa = sw[(4 * ic + 0) * 16 + jg];
            float4 wb = sw[(4 * ic + 1) * 16 + jg];
            float4 wc = sw[(4 * ic + 2) * 16 + jg];
            float4 wd = sw[(4 * ic + 3) * 16 + jg];
            acc.x += xv.x * wa.x + xv.y * wb.x + xv.z * wc.x + xv.w * wd.x;
            acc.y += xv.x * wa.y + xv.y * wb.y + xv.z * wc.y + xv.w * wd.y;
            acc.z += xv.x * wa.z + xv.y * wb.z + xv.z * wc.z + xv.w * wd.z;
            acc.w += xv.x * wa.w + xv.y * wb.w + xv.z * wc.w + xv.w * wd.w;
        }
        t4[jg] = relu4(acc);
    }
    __syncthreads();
    for (int idx = tid; idx < 1024; idx += 128)
        sw[idx] = __ldg(reinterpret_cast<const float4*>(w2) + idx);
    __syncthreads();

    int node = nbase + tid;
    if (node < N_NODES) {
        int g = __ldg(gids + node);
        float4* hrow = reinterpret_cast<float4*>(g_h1 + (size_t)node * H_F);
        float*  srow = g_sum1 + (size_t)g * H_F;
        const float4* b2v = reinterpret_cast<const float4*>(b2);
#pragma unroll 2
        for (int jg = 0; jg < 16; jg++) {
            float4 acc = __ldg(b2v + jg);
#pragma unroll
            for (int ic = 0; ic < 16; ic++) {
                float4 xv = t4[ic];
                float4 wa = sw[(4 * ic + 0) * 16 + jg];
                float4 wb = sw[(4 * ic + 1) * 16 + jg];
                float4 wc = sw[(4 * ic + 2) * 16 + jg];
                float4 wd = sw[(4 * ic + 3) * 16 + jg];
                acc.x += xv.x * wa.x + xv.y * wb.x + xv.z * wc.x + xv.w * wd.x;
                acc.y += xv.x * wa.y + xv.y * wb.y + xv.z * wc.y + xv.w * wd.y;
                acc.z += xv.x * wa.z + xv.y * wb.z + xv.z * wc.z + xv.w * wd.z;
                acc.w += xv.x * wa.w + xv.y * wb.w + xv.z * wc.w + xv.w * wd.w;
            }
            acc = relu4(acc);
            hrow[jg] = acc;
            red_add_v4(srow + jg * 4, acc);
        }
        atomicAdd(&g_cnt[g], 1.0f);
    }
}

// ============================================================================
// node MLP 2: x(64) = h1 + agg2 -> relu(W1 64) -> relu(W2 64), pools sum2.
// ============================================================================
__global__ __launch_bounds__(128)
void mlp2_kernel(const float* __restrict__ w1, const float* __restrict__ b1,
                 const float* __restrict__ w2, const float* __restrict__ b2,
                 const int* __restrict__ gids) {
    __shared__ float4 sx[128 * 16];   // 32 KB
    __shared__ float4 sw[64 * 16];    // 16 KB
    const int tid   = threadIdx.x;
    const int nbase = blockIdx.x * 128;

    for (int idx = tid; idx < 128 * 16; idx += 128) {
        int row = idx >> 4, c = idx & 15;
        int node = nbase + row;
        float4 v = make_float4(0.f, 0.f, 0.f, 0.f);
        if (node < N_NODES) {
            float4 a = *(reinterpret_cast<const float4*>(g_h1)   + (size_t)node * 16 + c);
            float4 b = *(reinterpret_cast<const float4*>(g_agg2) + (size_t)node * 16 + c);
            v = make_float4(a.x + b.x, a.y + b.y, a.z + b.z, a.w + b.w);
        }
        sx[row * 16 + (c ^ (row & 15))] = v;
    }
    for (int idx = tid; idx < 1024; idx += 128)
        sw[idx] = __ldg(reinterpret_cast<const float4*>(w1) + idx);
    __syncthreads();

    float4 t4[16];
    const int xb = tid * 16, k = tid & 15;
    const float4* b1v = reinterpret_cast<const float4*>(b1);
#pragma unroll
    for (int jg = 0; jg < 16; jg++) {
        float4 acc = __ldg(b1v + jg);
#pragma unroll
        for (int ic = 0; ic < 16; ic++) {
            float4 xv = sx[xb + (ic ^ k)];
            float4 wa = sw[(4 * ic + 0) * 16 + jg];
            float4 wb = sw[(4 * ic + 1) * 16 + jg];
            float4 wc = sw[(4 * ic + 2) * 16 + jg];
            float4 wd = sw[(4 * ic + 3) * 16 + jg];
            acc.x += xv.x * wa.x + xv.y * wb.x + xv.z * wc.x + xv.w * wd.x;
            acc.y += xv.x * wa.y + xv.y * wb.y + xv.z * wc.y + xv.w * wd.y;
            acc.z += xv.x * wa.z + xv.y * wb.z + xv.z * wc.z + xv.w * wd.z;
            acc.w += xv.x * wa.w + xv.y * wb.w + xv.z * wc.w + xv.w * wd.w;
        }
        t4[jg] = relu4(acc);
    }
    __syncthreads();
    for (int idx = tid; idx < 1024; idx += 128)
        sw[idx] = __ldg(reinterpret_cast<const float4*>(w2) + idx);
    __syncthreads();

    int node = nbase + tid;
    if (node < N_NODES) {
        int g = __ldg(gids + node);
        float* srow = g_sum2 + (size_t)g * H_F;
        const float4* b2v = reinterpret_cast<const float4*>(b2);
#pragma unroll 2
        for (int jg = 0; jg < 16; jg++) {
            float4 acc = __ldg(b2v + jg);
#pragma unroll
            for (int ic = 0; ic < 16; ic++) {
                float4 xv = t4[ic];
                float4 wa = sw[(4 * ic + 0) * 16 + jg];
                float4 wb = sw[(4 * ic + 1) * 16 + jg];
                float4 wc = sw[(4 * ic + 2) * 16 + jg];
                float4 wd = sw[(4 * ic + 3) * 16 + jg];
                acc.x += xv.x * wa.x + xv.y * wb.x + xv.z * wc.x + xv.w * wd.x;
                acc.y += xv.x * wa.y + xv.y * wb.y + xv.z * wc.y + xv.w * wd.y;
                acc.z += xv.x * wa.z + xv.y * wb.z + xv.z * wc.z + xv.w * wd.z;
                acc.w += xv.x * wa.w + xv.y * wb.w + xv.z * wc.w + xv.w * wd.w;
            }
            red_add_v4(srow + jg * 4, relu4(acc));
        }
    }
}

// ---------------- final tower: 8 graphs per block ----------------------------
#define GPB 8
__device__ __forceinline__ void lin8(const float (*x)[256], float (*y)[256],
                                     const float* __restrict__ w,
                                     const float* __restrict__ b,
                                     int nin, int nout, int t) {
    if (t < nout) {
        float a[GPB];
        float bb = b[t];
#pragma unroll
        for (int g = 0; g < GPB; g++) a[g] = bb;
        for (int i = 0; i < nin; i++) {
            float wv = __ldg(w + i * nout + t);
#pragma unroll
            for (int g = 0; g < GPB; g++) a[g] += wv * x[g][i];
        }
#pragma unroll
        for (int g = 0; g < GPB; g++) y[g][t] = fmaxf(a[g], 0.f);
    }
    __syncthreads();
}

__global__ __launch_bounds__(256)
void tower_kernel(const float* __restrict__ ev,
                  const float* __restrict__ l0w, const float* __restrict__ l0b,
                  const float* __restrict__ l1w, const float* __restrict__ l1b,
                  const float* __restrict__ l2w, const float* __restrict__ l2b,
                  const float* __restrict__ l3w, const float* __restrict__ l3b,
                  const float* __restrict__ l4w, const float* __restrict__ l4b,
                  const float* __restrict__ l5w, const float* __restrict__ l5b,
                  const float* __restrict__ l6w, const float* __restrict__ l6b,
                  float* __restrict__ out) {
    __shared__ float xa[GPB][256], xb[GPB][256];
    int g0 = blockIdx.x * GPB, t = threadIdx.x;

    if (t < 80) {
#pragma unroll
        for (int g = 0; g < GPB; g++) {
            int gg = g0 + g;
            if (t < H_F) {
                float c = fmaxf(g_cnt[gg], 1.f);
                xa[g][t] = (g_sum1[gg * H_F + t] + 2.f * g_sum2[gg * H_F + t]) / c;
            } else {
                xa[g][t] = __ldg(ev + gg * 16 + (t - 64));
            }
        }
    }
    __syncthreads();

    lin8(xa, xb, l0w, l0b,  80, 256, t);
    lin8(xb, xa, l1w, l1b, 256, 128, t);
    lin8(xa, xb, l2w, l2b, 128, 128, t);
    lin8(xb, xa, l3w, l3b, 128,  64, t);
    lin8(xa, xb, l4w, l4b,  64,  64, t);
    lin8(xb, xa, l5w, l5b,  64,  32, t);

    if (t < GPB) {
        float s = l6b[0];
#pragma unroll
        for (int i = 0; i < 32; i++) s += xa[t][i] * __ldg(l6w + i);
        out[g0 + t] = s;
    }
}

// ---------------- launch -----------------------------------------------------
extern "C" void kernel_launch(void* const* d_in, const int* in_sizes, int n_in,
                              void* d_out, int out_size) {
    const float* in_feat = (const float*)d_in[0];
    const float* ev      = (const float*)d_in[1];
    const int*   src     = (const int*)  d_in[2];
    const int*   dst     = (const int*)  d_in[3];
    const int*   gids    = (const int*)  d_in[4];
    const float* c0w1 = (const float*)d_in[5];
    const float* c0b1 = (const float*)d_in[6];
    const float* c0w2 = (const float*)d_in[7];
    const float* c0b2 = (const float*)d_in[8];
    const float* c1w1 = (const float*)d_in[9];
    const float* c1b1 = (const float*)d_in[10];
    const float* c1w2 = (const float*)d_in[11];
    const float* c1b2 = (const float*)d_in[12];
    const float* l0w = (const float*)d_in[13]; const float* l0b = (const float*)d_in[14];
    const float* l1w = (const float*)d_in[15]; const float* l1b = (const float*)d_in[16];
    const float* l2w = (const float*)d_in[17]; const float* l2b = (const float*)d_in[18];
    const float* l3w = (const float*)d_in[19]; const float* l3b = (const float*)d_in[20];
    const float* l4w = (const float*)d_in[21]; const float* l4b = (const float*)d_in[22];
    const float* l5w = (const float*)d_in[23]; const float* l5b = (const float*)d_in[24];
    const float* l6w = (const float*)d_in[25]; const float* l6b = (const float*)d_in[26];
    float* out = (float*)d_out;

    zero_kernel<<<(N_NODES + 255) / 256, 256>>>();
    deg_kernel<<<(N_EDGES + 255) / 256, 256>>>(dst);
    scan1_kernel<<<SCAN_NBLK, 256>>>();
    scan2_kernel<<<1, 512>>>();
    scan3_kernel<<<SCAN_NBLK, 256>>>();
    fill_kernel<<<(N_EDGES + 255) / 256, 256>>>(src, dst);

    gather1_kernel<<<(N_NODES * 32 + 255) / 256, 256>>>(in_feat);
    mlp1_kernel<<<(N_NODES + 127) / 128, 128>>>(in_feat, c0w1, c0b1, c0w2, c0b2, gids);

    gather2_kernel<<<(N_NODES * 32 + 255) / 256, 256>>>();
    mlp2_kernel<<<(N_NODES + 127) / 128, 128>>>(c1w1, c1b1, c1w2, c1b2, gids);

    tower_kernel<<<NB / GPB, 256>>>(ev,
                                    l0w, l0b, l1w, l1b, l2w, l2b, l3w, l3b,
                                    l4w, l4b, l5w, l5b, l6w, l6b, out);
}

// round 13
// speedup vs baseline: 1.0682x; 1.0682x over previous
#include <cuda_runtime.h>

#define N_NODES 100000
#define N_EDGES 1600000
#define NB      1024
#define IN_F    32
#define H_F     64

// ---------------- scratch (device globals; no allocations allowed) ----------
__device__ int   g_deg [N_NODES];
__device__ int   g_off [N_NODES];
__device__ int   g_cur [N_NODES];
__device__ int   g_csr [N_EDGES];           // src ids grouped by dst (order-free)
__device__ int   g_total;
__device__ __align__(256) float g_agg1[N_NODES * IN_F];  // 12.8 MB
__device__ __align__(256) float g_agg2[N_NODES * H_F];   // 25.6 MB
__device__ __align__(256) float g_h1  [N_NODES * H_F];   // 25.6 MB
__device__ __align__(256) float g_sum1[NB * H_F];
__device__ __align__(256) float g_sum2[NB * H_F];
__device__ __align__(256) float g_cnt [NB];

__device__ __forceinline__ void red_add_v4(float* addr, float4 v) {
    asm volatile("red.global.add.v4.f32 [%0], {%1, %2, %3, %4};"
                 :: "l"(addr), "f"(v.x), "f"(v.y), "f"(v.z), "f"(v.w)
                 : "memory");
}
__device__ __forceinline__ float4 relu4(float4 a) {
    return make_float4(fmaxf(a.x, 0.f), fmaxf(a.y, 0.f),
                       fmaxf(a.z, 0.f), fmaxf(a.w, 0.f));
}

// ---------------- zero: deg + pools + total ----------------------------------
__global__ void zero_kernel() {
    int gid = blockIdx.x * blockDim.x + threadIdx.x;
    if (gid < N_NODES) g_deg[gid] = 0;
    float4 z = make_float4(0.f, 0.f, 0.f, 0.f);
    if (gid < NB * H_F / 4) {
        reinterpret_cast<float4*>(g_sum1)[gid] = z;
        reinterpret_cast<float4*>(g_sum2)[gid] = z;
    }
    if (gid < NB / 4)
        reinterpret_cast<float4*>(g_cnt)[gid] = z;
    if (gid == 0) g_total = 0;
}

// ---------------- CSR build: deg -> atomic offsets -> fill -------------------
__global__ void deg_kernel(const int* __restrict__ dst) {
    int e = blockIdx.x * blockDim.x + threadIdx.x;
    if (e < N_EDGES) atomicAdd(&g_deg[__ldg(dst + e)], 1);
}

// Segment order within g_csr is irrelevant to the gathers — each node only
// needs a private contiguous range. One atomic pass replaces the 3-kernel scan.
__global__ void offs_kernel() {
    int n = blockIdx.x * blockDim.x + threadIdx.x;
    if (n >= N_NODES) return;
    int d = g_deg[n];
    int off = atomicAdd(&g_total, d);
    g_off[n] = off;
    g_cur[n] = off;
}

__global__ void fill_kernel(const int* __restrict__ src,
                            const int* __restrict__ dst) {
    int e = blockIdx.x * blockDim.x + threadIdx.x;
    if (e >= N_EDGES) return;
    int d = __ldg(dst + e);
    int pos = atomicAdd(&g_cur[d], 1);
    g_csr[pos] = __ldg(src + e);
}

// ---------------- gather 1: warp per node, lane = feature, unroll 4 ----------
// (R9-validated form: direct batched loads; shfl/fp16 variants measured slower)
__global__ __launch_bounds__(256)
void gather1_kernel(const float* __restrict__ feat) {
    int n = (blockIdx.x * 256 + threadIdx.x) >> 5;
    int lane = threadIdx.x & 31;
    if (n >= N_NODES) return;
    int st = __ldg(&g_off[n]);
    int dg = __ldg(&g_deg[n]);
    float acc = 0.f;
    int i = 0;
    for (; i + 4 <= dg; i += 4) {
        int s0 = __ldg(g_csr + st + i);
        int s1 = __ldg(g_csr + st + i + 1);
        int s2 = __ldg(g_csr + st + i + 2);
        int s3 = __ldg(g_csr + st + i + 3);
        float a0 = __ldg(feat + (size_t)s0 * IN_F + lane);
        float a1 = __ldg(feat + (size_t)s1 * IN_F + lane);
        float a2 = __ldg(feat + (size_t)s2 * IN_F + lane);
        float a3 = __ldg(feat + (size_t)s3 * IN_F + lane);
        acc += (a0 + a1) + (a2 + a3);
    }
    for (; i < dg; i++) {
        int s = __ldg(g_csr + st + i);
        acc += __ldg(feat + (size_t)s * IN_F + lane);
    }
    g_agg1[(size_t)n * IN_F + lane] = acc;
}

// ---------------- gather 2: warp per node, lane = float2 chunk, unroll 4 -----
__global__ __launch_bounds__(256)
void gather2_kernel() {
    int n = (blockIdx.x * 256 + threadIdx.x) >> 5;
    int lane = threadIdx.x & 31;
    if (n >= N_NODES) return;
    int st = __ldg(&g_off[n]);
    int dg = __ldg(&g_deg[n]);
    const float2* h1v = reinterpret_cast<const float2*>(g_h1);
    float2 acc = make_float2(0.f, 0.f);
    int i = 0;
    for (; i + 4 <= dg; i += 4) {
        int s0 = __ldg(g_csr + st + i);
        int s1 = __ldg(g_csr + st + i + 1);
        int s2 = __ldg(g_csr + st + i + 2);
        int s3 = __ldg(g_csr + st + i + 3);
        float2 a0 = h1v[(size_t)s0 * 32 + lane];
        float2 a1 = h1v[(size_t)s1 * 32 + lane];
        float2 a2 = h1v[(size_t)s2 * 32 + lane];
        float2 a3 = h1v[(size_t)s3 * 32 + lane];
        acc.x += (a0.x + a1.x) + (a2.x + a3.x);
        acc.y += (a0.y + a1.y) + (a2.y + a3.y);
    }
    for (; i < dg; i++) {
        int s = __ldg(g_csr + st + i);
        float2 a = h1v[(size_t)s * 32 + lane];
        acc.x += a.x; acc.y += a.y;
    }
    reinterpret_cast<float2*>(g_agg2)[(size_t)n * 32 + lane] = acc;
}

// ============================================================================
// node MLP 1: x(32) = in_feat + agg1 -> relu(W1 64) -> relu(W2 64)
// writes h1, pools sum1, counts.
// ============================================================================
__global__ __launch_bounds__(128)
void mlp1_kernel(const float* __restrict__ in_feat,
                 const float* __restrict__ w1, const float* __restrict__ b1,
                 const float* __restrict__ w2, const float* __restrict__ b2,
                 const int* __restrict__ gids) {
    __shared__ float4 sx[128 * 8];    // 16 KB
    __shared__ float4 sw[64 * 16];    // 16 KB
    const int tid   = threadIdx.x;
    const int nbase = blockIdx.x * 128;

    for (int idx = tid; idx < 128 * 8; idx += 128) {
        int row = idx >> 3, c = idx & 7;
        int node = nbase + row;
        float4 v = make_float4(0.f, 0.f, 0.f, 0.f);
        if (node < N_NODES) {
            float4 a = __ldg(reinterpret_cast<const float4*>(in_feat) + (size_t)node * 8 + c);
            float4 b = *(reinterpret_cast<const float4*>(g_agg1) + (size_t)node * 8 + c);
            v = make_float4(a.x + b.x, a.y + b.y, a.z + b.z, a.w + b.w);
        }
        sx[row * 8 + (c ^ (row & 7))] = v;
    }
    for (int idx = tid; idx < 512; idx += 128)
        sw[idx] = __ldg(reinterpret_cast<const float4*>(w1) + idx);
    __syncthreads();

    float4 t4[16];
    const int xb = tid * 8, k1 = tid & 7;
    const float4* b1v = reinterpret_cast<const float4*>(b1);
#pragma unroll
    for (int jg = 0; jg < 16; jg++) {
        float4 acc = __ldg(b1v + jg);
#pragma unroll
        for (int ic = 0; ic < 8; ic++) {
            float4 xv = sx[xb + (ic ^ k1)];
            float4 wa = sw[(4 * ic + 0) * 16 + jg];
            float4 wb = sw[(4 * ic + 1) * 16 + jg];
            float4 wc = sw[(4 * ic + 2) * 16 + jg];
            float4 wd = sw[(4 * ic + 3) * 16 + jg];
            acc.x += xv.x * wa.x + xv.y * wb.x + xv.z * wc.x + xv.w * wd.x;
            acc.y += xv.x * wa.y + xv.y * wb.y + xv.z * wc.y + xv.w * wd.y;
            acc.z += xv.x * wa.z + xv.y * wb.z + xv.z * wc.z + xv.w * wd.z;
            acc.w += xv.x * wa.w + xv.y * wb.w + xv.z * wc.w + xv.w * wd.w;
        }
        t4[jg] = relu4(acc);
    }
    __syncthreads();
    for (int idx = tid; idx < 1024; idx += 128)
        sw[idx] = __ldg(reinterpret_cast<const float4*>(w2) + idx);
    __syncthreads();

    int node = nbase + tid;
    if (node < N_NODES) {
        int g = __ldg(gids + node);
        float4* hrow = reinterpret_cast<float4*>(g_h1 + (size_t)node * H_F);
        float*  srow = g_sum1 + (size_t)g * H_F;
        const float4* b2v = reinterpret_cast<const float4*>(b2);
#pragma unroll 2
        for (int jg = 0; jg < 16; jg++) {
            float4 acc = __ldg(b2v + jg);
#pragma unroll
            for (int ic = 0; ic < 16; ic++) {
                float4 xv = t4[ic];
                float4 wa = sw[(4 * ic + 0) * 16 + jg];
                float4 wb = sw[(4 * ic + 1) * 16 + jg];
                float4 wc = sw[(4 * ic + 2) * 16 + jg];
                float4 wd = sw[(4 * ic + 3) * 16 + jg];
                acc.x += xv.x * wa.x + xv.y * wb.x + xv.z * wc.x + xv.w * wd.x;
                acc.y += xv.x * wa.y + xv.y * wb.y + xv.z * wc.y + xv.w * wd.y;
                acc.z += xv.x * wa.z + xv.y * wb.z + xv.z * wc.z + xv.w * wd.z;
                acc.w += xv.x * wa.w + xv.y * wb.w + xv.z * wc.w + xv.w * wd.w;
            }
            acc = relu4(acc);
            hrow[jg] = acc;
            red_add_v4(srow + jg * 4, acc);
        }
        atomicAdd(&g_cnt[g], 1.0f);
    }
}

// ============================================================================
// node MLP 2: x(64) = h1 + agg2 -> relu(W1 64) -> relu(W2 64), pools sum2.
// ============================================================================
__global__ __launch_bounds__(128)
void mlp2_kernel(const float* __restrict__ w1, const float* __restrict__ b1,
                 const float* __restrict__ w2, const float* __restrict__ b2,
                 const int* __restrict__ gids) {
    __shared__ float4 sx[128 * 16];   // 32 KB
    __shared__ float4 sw[64 * 16];    // 16 KB
    const int tid   = threadIdx.x;
    const int nbase = blockIdx.x * 128;

    for (int idx = tid; idx < 128 * 16; idx += 128) {
        int row = idx >> 4, c = idx & 15;
        int node = nbase + row;
        float4 v = make_float4(0.f, 0.f, 0.f, 0.f);
        if (node < N_NODES) {
            float4 a = *(reinterpret_cast<const float4*>(g_h1)   + (size_t)node * 16 + c);
            float4 b = *(reinterpret_cast<const float4*>(g_agg2) + (size_t)node * 16 + c);
            v = make_float4(a.x + b.x, a.y + b.y, a.z + b.z, a.w + b.w);
        }
        sx[row * 16 + (c ^ (row & 15))] = v;
    }
    for (int idx = tid; idx < 1024; idx += 128)
        sw[idx] = __ldg(reinterpret_cast<const float4*>(w1) + idx);
    __syncthreads();

    float4 t4[16];
    const int xb = tid * 16, k = tid & 15;
    const float4* b1v = reinterpret_cast<const float4*>(b1);
#pragma unroll
    for (int jg = 0; jg < 16; jg++) {
        float4 acc = __ldg(b1v + jg);
#pragma unroll
        for (int ic = 0; ic < 16; ic++) {
            float4 xv = sx[xb + (ic ^ k)];
            float4 wa = sw[(4 * ic + 0) * 16 + jg];
            float4 wb = sw[(4 * ic + 1) * 16 + jg];
            float4 wc = sw[(4 * ic + 2) * 16 + jg];
            float4 wd = sw[(4 * ic + 3) * 16 + jg];
            acc.x += xv.x * wa.x + xv.y * wb.x + xv.z * wc.x + xv.w * wd.x;
            acc.y += xv.x * wa.y + xv.y * wb.y + xv.z * wc.y + xv.w * wd.y;
            acc.z += xv.x * wa.z + xv.y * wb.z + xv.z * wc.z + xv.w * wd.z;
            acc.w += xv.x * wa.w + xv.y * wb.w + xv.z * wc.w + xv.w * wd.w;
        }
        t4[jg] = relu4(acc);
    }
    __syncthreads();
    for (int idx = tid; idx < 1024; idx += 128)
        sw[idx] = __ldg(reinterpret_cast<const float4*>(w2) + idx);
    __syncthreads();

    int node = nbase + tid;
    if (node < N_NODES) {
        int g = __ldg(gids + node);
        float* srow = g_sum2 + (size_t)g * H_F;
        const float4* b2v = reinterpret_cast<const float4*>(b2);
#pragma unroll 2
        for (int jg = 0; jg < 16; jg++) {
            float4 acc = __ldg(b2v + jg);
#pragma unroll
            for (int ic = 0; ic < 16; ic++) {
                float4 xv = t4[ic];
                float4 wa = sw[(4 * ic + 0) * 16 + jg];
                float4 wb = sw[(4 * ic + 1) * 16 + jg];
                float4 wc = sw[(4 * ic + 2) * 16 + jg];
                float4 wd = sw[(4 * ic + 3) * 16 + jg];
                acc.x += xv.x * wa.x + xv.y * wb.x + xv.z * wc.x + xv.w * wd.x;
                acc.y += xv.x * wa.y + xv.y * wb.y + xv.z * wc.y + xv.w * wd.y;
                acc.z += xv.x * wa.z + xv.y * wb.z + xv.z * wc.z + xv.w * wd.z;
                acc.w += xv.x * wa.w + xv.y * wb.w + xv.z * wc.w + xv.w * wd.w;
            }
            red_add_v4(srow + jg * 4, relu4(acc));
        }
    }
}

// ---------------- final tower: 4 graphs per block (R9-validated) -------------
#define GPB 4
__device__ __forceinline__ void lin4(const float (*x)[256], float (*y)[256],
                                     const float* __restrict__ w,
                                     const float* __restrict__ b,
                                     int nin, int nout, int t) {
    if (t < nout) {
        float a0 = b[t], a1 = a0, a2 = a0, a3 = a0;
        for (int i = 0; i < nin; i++) {
            float wv = __ldg(w + i * nout + t);
            a0 += wv * x[0][i];
            a1 += wv * x[1][i];
            a2 += wv * x[2][i];
            a3 += wv * x[3][i];
        }
        y[0][t] = fmaxf(a0, 0.f);
        y[1][t] = fmaxf(a1, 0.f);
        y[2][t] = fmaxf(a2, 0.f);
        y[3][t] = fmaxf(a3, 0.f);
    }
    __syncthreads();
}

__global__ __launch_bounds__(256)
void tower_kernel(const float* __restrict__ ev,
                  const float* __restrict__ l0w, const float* __restrict__ l0b,
                  const float* __restrict__ l1w, const float* __restrict__ l1b,
                  const float* __restrict__ l2w, const float* __restrict__ l2b,
                  const float* __restrict__ l3w, const float* __restrict__ l3b,
                  const float* __restrict__ l4w, const float* __restrict__ l4b,
                  const float* __restrict__ l5w, const float* __restrict__ l5b,
                  const float* __restrict__ l6w, const float* __restrict__ l6b,
                  float* __restrict__ out) {
    __shared__ float xa[GPB][256], xb[GPB][256];
    int g0 = blockIdx.x * GPB, t = threadIdx.x;

    if (t < 80) {
#pragma unroll
        for (int g = 0; g < GPB; g++) {
            int gg = g0 + g;
            if (t < H_F) {
                float c = fmaxf(g_cnt[gg], 1.f);
                xa[g][t] = (g_sum1[gg * H_F + t] + 2.f * g_sum2[gg * H_F + t]) / c;
            } else {
                xa[g][t] = __ldg(ev + gg * 16 + (t - 64));
            }
        }
    }
    __syncthreads();

    lin4(xa, xb, l0w, l0b,  80, 256, t);
    lin4(xb, xa, l1w, l1b, 256, 128, t);
    lin4(xa, xb, l2w, l2b, 128, 128, t);
    lin4(xb, xa, l3w, l3b, 128,  64, t);
    lin4(xa, xb, l4w, l4b,  64,  64, t);
    lin4(xb, xa, l5w, l5b,  64,  32, t);

    if (t < GPB) {
        float s = l6b[0];
#pragma unroll
        for (int i = 0; i < 32; i++) s += xa[t][i] * __ldg(l6w + i);
        out[g0 + t] = s;
    }
}

// ---------------- launch -----------------------------------------------------
extern "C" void kernel_launch(void* const* d_in, const int* in_sizes, int n_in,
                              void* d_out, int out_size) {
    const float* in_feat = (const float*)d_in[0];
    const float* ev      = (const float*)d_in[1];
    const int*   src     = (const int*)  d_in[2];
    const int*   dst     = (const int*)  d_in[3];
    const int*   gids    = (const int*)  d_in[4];
    const float* c0w1 = (const float*)d_in[5];
    const float* c0b1 = (const float*)d_in[6];
    const float* c0w2 = (const float*)d_in[7];
    const float* c0b2 = (const float*)d_in[8];
    const float* c1w1 = (const float*)d_in[9];
    const float* c1b1 = (const float*)d_in[10];
    const float* c1w2 = (const float*)d_in[11];
    const float* c1b2 = (const float*)d_in[12];
    const float* l0w = (const float*)d_in[13]; const float* l0b = (const float*)d_in[14];
    const float* l1w = (const float*)d_in[15]; const float* l1b = (const float*)d_in[16];
    const float* l2w = (const float*)d_in[17]; const float* l2b = (const float*)d_in[18];
    const float* l3w = (const float*)d_in[19]; const float* l3b = (const float*)d_in[20];
    const float* l4w = (const float*)d_in[21]; const float* l4b = (const float*)d_in[22];
    const float* l5w = (const float*)d_in[23]; const float* l5b = (const float*)d_in[24];
    const float* l6w = (const float*)d_in[25]; const float* l6b = (const float*)d_in[26];
    float* out = (float*)d_out;

    zero_kernel<<<(N_NODES + 255) / 256, 256>>>();
    deg_kernel<<<(N_EDGES + 255) / 256, 256>>>(dst);
    offs_kernel<<<(N_NODES + 255) / 256, 256>>>();
    fill_kernel<<<(N_EDGES + 255) / 256, 256>>>(src, dst);

    gather1_kernel<<<(N_NODES * 32 + 255) / 256, 256>>>(in_feat);
    mlp1_kernel<<<(N_NODES + 127) / 128, 128>>>(in_feat, c0w1, c0b1, c0w2, c0b2, gids);

    gather2_kernel<<<(N_NODES * 32 + 255) / 256, 256>>>();
    mlp2_kernel<<<(N_NODES + 127) / 128, 128>>>(c1w1, c1b1, c1w2, c1b2, gids);

    tower_kernel<<<NB / GPB, 256>>>(ev,
                                    l0w, l0b, l1w, l1b, l2w, l2b, l3w, l3b,
                                    l4w, l4b, l5w, l5b, l6w, l6b, out);
}

// round 14
// speedup vs baseline: 1.0871x; 1.0177x over previous
#include <cuda_runtime.h>
#include <cstdint>

#define N_NODES 100000
#define N_EDGES 1600000
#define NB      1024
#define IN_F    32
#define H_F     64

// ---------------- scratch (device globals; zero-initialized .bss) -----------
__device__ int   g_deg [N_NODES];
__device__ int   g_off [N_NODES];
__device__ int   g_cur [N_NODES];
__device__ int   g_csr [N_EDGES];           // src ids grouped by dst (order-free)
__device__ int   g_total;
__device__ __align__(256) float g_agg1[N_NODES * IN_F];  // 12.8 MB
__device__ __align__(256) float g_agg2[N_NODES * H_F];   // 25.6 MB
__device__ __align__(256) float g_h1  [N_NODES * H_F];   // 25.6 MB
__device__ __align__(256) float g_sum1[NB * H_F];
__device__ __align__(256) float g_sum2[NB * H_F];
__device__ __align__(256) float g_cnt [NB];

__device__ __forceinline__ void red_add_v4(float* addr, float4 v) {
    asm volatile("red.global.add.v4.f32 [%0], {%1, %2, %3, %4};"
                 :: "l"(addr), "f"(v.x), "f"(v.y), "f"(v.z), "f"(v.w)
                 : "memory");
}
__device__ __forceinline__ float4 relu4(float4 a) {
    return make_float4(fmaxf(a.x, 0.f), fmaxf(a.y, 0.f),
                       fmaxf(a.z, 0.f), fmaxf(a.w, 0.f));
}
// ---- packed f32x2 (sm_100 FFMA2 path) ----
__device__ __forceinline__ uint64_t pack2(float a, float b) {
    uint64_t r; asm("mov.b64 %0, {%1, %2};" : "=l"(r) : "f"(a), "f"(b)); return r;
}
__device__ __forceinline__ void fma2(uint64_t& d, uint64_t a, uint64_t b) {
    asm("fma.rn.f32x2 %0, %1, %2, %0;" : "+l"(d) : "l"(a), "l"(b));
}
__device__ __forceinline__ float2 unpack2(uint64_t v) {
    float2 r; asm("mov.b64 {%0, %1}, %2;" : "=f"(r.x), "=f"(r.y) : "l"(v)); return r;
}

// ---------------- CSR build: deg -> atomic offsets -> fill -------------------
// g_deg/g_total arrive zeroed (initial .bss, then re-zeroed by tower_kernel).
__global__ void deg_kernel(const int* __restrict__ dst) {
    int e = blockIdx.x * blockDim.x + threadIdx.x;
    if (e < N_EDGES) atomicAdd(&g_deg[__ldg(dst + e)], 1);
}

__global__ void offs_kernel() {
    int n = blockIdx.x * blockDim.x + threadIdx.x;
    if (n >= N_NODES) return;
    int d = g_deg[n];
    int off = atomicAdd(&g_total, d);
    g_off[n] = off;
    g_cur[n] = off;
}

__global__ void fill_kernel(const int* __restrict__ src,
                            const int* __restrict__ dst) {
    int e = blockIdx.x * blockDim.x + threadIdx.x;
    if (e >= N_EDGES) return;
    int d = __ldg(dst + e);
    int pos = atomicAdd(&g_cur[d], 1);
    g_csr[pos] = __ldg(src + e);
}

// ---------------- gather 1: warp per node, lane = feature, unroll 4 ----------
__global__ __launch_bounds__(256)
void gather1_kernel(const float* __restrict__ feat) {
    int n = (blockIdx.x * 256 + threadIdx.x) >> 5;
    int lane = threadIdx.x & 31;
    if (n >= N_NODES) return;
    int st = __ldg(&g_off[n]);
    int dg = __ldg(&g_deg[n]);
    float acc = 0.f;
    int i = 0;
    for (; i + 4 <= dg; i += 4) {
        int s0 = __ldg(g_csr + st + i);
        int s1 = __ldg(g_csr + st + i + 1);
        int s2 = __ldg(g_csr + st + i + 2);
        int s3 = __ldg(g_csr + st + i + 3);
        float a0 = __ldg(feat + (size_t)s0 * IN_F + lane);
        float a1 = __ldg(feat + (size_t)s1 * IN_F + lane);
        float a2 = __ldg(feat + (size_t)s2 * IN_F + lane);
        float a3 = __ldg(feat + (size_t)s3 * IN_F + lane);
        acc += (a0 + a1) + (a2 + a3);
    }
    for (; i < dg; i++) {
        int s = __ldg(g_csr + st + i);
        acc += __ldg(feat + (size_t)s * IN_F + lane);
    }
    g_agg1[(size_t)n * IN_F + lane] = acc;
}

// ---------------- gather 2: warp per node, lane = float2 chunk, unroll 4 -----
__global__ __launch_bounds__(256)
void gather2_kernel() {
    int n = (blockIdx.x * 256 + threadIdx.x) >> 5;
    int lane = threadIdx.x & 31;
    if (n >= N_NODES) return;
    int st = __ldg(&g_off[n]);
    int dg = __ldg(&g_deg[n]);
    const float2* h1v = reinterpret_cast<const float2*>(g_h1);
    float2 acc = make_float2(0.f, 0.f);
    int i = 0;
    for (; i + 4 <= dg; i += 4) {
        int s0 = __ldg(g_csr + st + i);
        int s1 = __ldg(g_csr + st + i + 1);
        int s2 = __ldg(g_csr + st + i + 2);
        int s3 = __ldg(g_csr + st + i + 3);
        float2 a0 = h1v[(size_t)s0 * 32 + lane];
        float2 a1 = h1v[(size_t)s1 * 32 + lane];
        float2 a2 = h1v[(size_t)s2 * 32 + lane];
        float2 a3 = h1v[(size_t)s3 * 32 + lane];
        acc.x += (a0.x + a1.x) + (a2.x + a3.x);
        acc.y += (a0.y + a1.y) + (a2.y + a3.y);
    }
    for (; i < dg; i++) {
        int s = __ldg(g_csr + st + i);
        float2 a = h1v[(size_t)s * 32 + lane];
        acc.x += a.x; acc.y += a.y;
    }
    reinterpret_cast<float2*>(g_agg2)[(size_t)n * 32 + lane] = acc;
}

// ---- packed inner product step: acc(4) += x[c] * w[4*ic+c][jg], c=0..3 ------
__device__ __forceinline__ void mlp_step(uint64_t& a01, uint64_t& a23,
                                         float4 xv, const float4* sw,
                                         int ic, int jg) {
    const ulonglong2* wp = reinterpret_cast<const ulonglong2*>(sw);
    ulonglong2 w0 = wp[(4 * ic + 0) * 16 + jg];
    ulonglong2 w1 = wp[(4 * ic + 1) * 16 + jg];
    ulonglong2 w2 = wp[(4 * ic + 2) * 16 + jg];
    ulonglong2 w3 = wp[(4 * ic + 3) * 16 + jg];
    uint64_t x0 = pack2(xv.x, xv.x), x1 = pack2(xv.y, xv.y);
    uint64_t x2 = pack2(xv.z, xv.z), x3 = pack2(xv.w, xv.w);
    fma2(a01, x0, w0.x); fma2(a23, x0, w0.y);
    fma2(a01, x1, w1.x); fma2(a23, x1, w1.y);
    fma2(a01, x2, w2.x); fma2(a23, x2, w2.y);
    fma2(a01, x3, w3.x); fma2(a23, x3, w3.y);
}

// ============================================================================
// node MLP 1: x(32) = in_feat + agg1 -> relu(W1 64) -> relu(W2 64)
// writes h1, pools sum1, counts.  (FFMA2 inner product)
// ============================================================================
__global__ __launch_bounds__(128)
void mlp1_kernel(const float* __restrict__ in_feat,
                 const float* __restrict__ w1, const float* __restrict__ b1,
                 const float* __restrict__ w2, const float* __restrict__ b2,
                 const int* __restrict__ gids) {
    __shared__ float4 sx[128 * 8];    // 16 KB
    __shared__ float4 sw[64 * 16];    // 16 KB
    const int tid   = threadIdx.x;
    const int nbase = blockIdx.x * 128;

    for (int idx = tid; idx < 128 * 8; idx += 128) {
        int row = idx >> 3, c = idx & 7;
        int node = nbase + row;
        float4 v = make_float4(0.f, 0.f, 0.f, 0.f);
        if (node < N_NODES) {
            float4 a = __ldg(reinterpret_cast<const float4*>(in_feat) + (size_t)node * 8 + c);
            float4 b = *(reinterpret_cast<const float4*>(g_agg1) + (size_t)node * 8 + c);
            v = make_float4(a.x + b.x, a.y + b.y, a.z + b.z, a.w + b.w);
        }
        sx[row * 8 + (c ^ (row & 7))] = v;
    }
    for (int idx = tid; idx < 512; idx += 128)
        sw[idx] = __ldg(reinterpret_cast<const float4*>(w1) + idx);
    __syncthreads();

    float4 t4[16];
    const int xb = tid * 8, k1 = tid & 7;
    const float4* b1v = reinterpret_cast<const float4*>(b1);
#pragma unroll
    for (int jg = 0; jg < 16; jg++) {
        float4 bv = __ldg(b1v + jg);
        uint64_t a01 = pack2(bv.x, bv.y), a23 = pack2(bv.z, bv.w);
#pragma unroll
        for (int ic = 0; ic < 8; ic++)
            mlp_step(a01, a23, sx[xb + (ic ^ k1)], sw, ic, jg);
        float2 p = unpack2(a01), q = unpack2(a23);
        t4[jg] = relu4(make_float4(p.x, p.y, q.x, q.y));
    }
    __syncthreads();
    for (int idx = tid; idx < 1024; idx += 128)
        sw[idx] = __ldg(reinterpret_cast<const float4*>(w2) + idx);
    __syncthreads();

    int node = nbase + tid;
    if (node < N_NODES) {
        int g = __ldg(gids + node);
        float4* hrow = reinterpret_cast<float4*>(g_h1 + (size_t)node * H_F);
        float*  srow = g_sum1 + (size_t)g * H_F;
        const float4* b2v = reinterpret_cast<const float4*>(b2);
#pragma unroll 2
        for (int jg = 0; jg < 16; jg++) {
            float4 bv = __ldg(b2v + jg);
            uint64_t a01 = pack2(bv.x, bv.y), a23 = pack2(bv.z, bv.w);
#pragma unroll
            for (int ic = 0; ic < 16; ic++)
                mlp_step(a01, a23, t4[ic], sw, ic, jg);
            float2 p = unpack2(a01), q = unpack2(a23);
            float4 acc = relu4(make_float4(p.x, p.y, q.x, q.y));
            hrow[jg] = acc;
            red_add_v4(srow + jg * 4, acc);
        }
        atomicAdd(&g_cnt[g], 1.0f);
    }
}

// ============================================================================
// node MLP 2: x(64) = h1 + agg2 -> relu(W1 64) -> relu(W2 64), pools sum2.
// ============================================================================
__global__ __launch_bounds__(128)
void mlp2_kernel(const float* __restrict__ w1, const float* __restrict__ b1,
                 const float* __restrict__ w2, const float* __restrict__ b2,
                 const int* __restrict__ gids) {
    __shared__ float4 sx[128 * 16];   // 32 KB
    __shared__ float4 sw[64 * 16];    // 16 KB
    const int tid   = threadIdx.x;
    const int nbase = blockIdx.x * 128;

    for (int idx = tid; idx < 128 * 16; idx += 128) {
        int row = idx >> 4, c = idx & 15;
        int node = nbase + row;
        float4 v = make_float4(0.f, 0.f, 0.f, 0.f);
        if (node < N_NODES) {
            float4 a = *(reinterpret_cast<const float4*>(g_h1)   + (size_t)node * 16 + c);
            float4 b = *(reinterpret_cast<const float4*>(g_agg2) + (size_t)node * 16 + c);
            v = make_float4(a.x + b.x, a.y + b.y, a.z + b.z, a.w + b.w);
        }
        sx[row * 16 + (c ^ (row & 15))] = v;
    }
    for (int idx = tid; idx < 1024; idx += 128)
        sw[idx] = __ldg(reinterpret_cast<const float4*>(w1) + idx);
    __syncthreads();

    float4 t4[16];
    const int xb = tid * 16, k = tid & 15;
    const float4* b1v = reinterpret_cast<const float4*>(b1);
#pragma unroll
    for (int jg = 0; jg < 16; jg++) {
        float4 bv = __ldg(b1v + jg);
        uint64_t a01 = pack2(bv.x, bv.y), a23 = pack2(bv.z, bv.w);
#pragma unroll
        for (int ic = 0; ic < 16; ic++)
            mlp_step(a01, a23, sx[xb + (ic ^ k)], sw, ic, jg);
        float2 p = unpack2(a01), q = unpack2(a23);
        t4[jg] = relu4(make_float4(p.x, p.y, q.x, q.y));
    }
    __syncthreads();
    for (int idx = tid; idx < 1024; idx += 128)
        sw[idx] = __ldg(reinterpret_cast<const float4*>(w2) + idx);
    __syncthreads();

    int node = nbase + tid;
    if (node < N_NODES) {
        int g = __ldg(gids + node);
        float* srow = g_sum2 + (size_t)g * H_F;
        const float4* b2v = reinterpret_cast<const float4*>(b2);
#pragma unroll 2
        for (int jg = 0; jg < 16; jg++) {
            float4 bv = __ldg(b2v + jg);
            uint64_t a01 = pack2(bv.x, bv.y), a23 = pack2(bv.z, bv.w);
#pragma unroll
            for (int ic = 0; ic < 16; ic++)
                mlp_step(a01, a23, t4[ic], sw, ic, jg);
            float2 p = unpack2(a01), q = unpack2(a23);
            red_add_v4(srow + jg * 4, relu4(make_float4(p.x, p.y, q.x, q.y)));
        }
    }
}

// ---------------- final tower: 4 graphs per block + state re-zeroing ---------
#define GPB 4
__device__ __forceinline__ void lin4(const float (*x)[256], float (*y)[256],
                                     const float* __restrict__ w,
                                     const float* __restrict__ b,
                                     int nin, int nout, int t) {
    if (t < nout) {
        float a0 = b[t], a1 = a0, a2 = a0, a3 = a0;
        for (int i = 0; i < nin; i++) {
            float wv = __ldg(w + i * nout + t);
            a0 += wv * x[0][i];
            a1 += wv * x[1][i];
            a2 += wv * x[2][i];
            a3 += wv * x[3][i];
        }
        y[0][t] = fmaxf(a0, 0.f);
        y[1][t] = fmaxf(a1, 0.f);
        y[2][t] = fmaxf(a2, 0.f);
        y[3][t] = fmaxf(a3, 0.f);
    }
    __syncthreads();
}

__global__ __launch_bounds__(256)
void tower_kernel(const float* __restrict__ ev,
                  const float* __restrict__ l0w, const float* __restrict__ l0b,
                  const float* __restrict__ l1w, const float* __restrict__ l1b,
                  const float* __restrict__ l2w, const float* __restrict__ l2b,
                  const float* __restrict__ l3w, const float* __restrict__ l3b,
                  const float* __restrict__ l4w, const float* __restrict__ l4b,
                  const float* __restrict__ l5w, const float* __restrict__ l5b,
                  const float* __restrict__ l6w, const float* __restrict__ l6b,
                  float* __restrict__ out) {
    __shared__ float xa[GPB][256], xb[GPB][256];
    int g0 = blockIdx.x * GPB, t = threadIdx.x;

    if (t < 80) {
#pragma unroll
        for (int g = 0; g < GPB; g++) {
            int gg = g0 + g;
            if (t < H_F) {
                float c = fmaxf(g_cnt[gg], 1.f);
                xa[g][t] = (g_sum1[gg * H_F + t] + 2.f * g_sum2[gg * H_F + t]) / c;
            } else {
                xa[g][t] = __ldg(ev + gg * 16 + (t - 64));
            }
        }
    }
    __syncthreads();

    // re-zero state for the next graph replay (this block's slice only; the
    // reads above are complete past the barrier). g_deg/g_total are not read
    // by this kernel, so any partition works.
    g_sum1[g0 * H_F + t] = 0.f;        // 4 graphs * 64 = 256 = blockDim
    g_sum2[g0 * H_F + t] = 0.f;
    if (t < GPB) g_cnt[g0 + t] = 0.f;
    for (int i = blockIdx.x * 256 + t; i < N_NODES; i += NB / GPB * 256)
        g_deg[i] = 0;
    if (blockIdx.x == 0 && t == 0) g_total = 0;

    lin4(xa, xb, l0w, l0b,  80, 256, t);
    lin4(xb, xa, l1w, l1b, 256, 128, t);
    lin4(xa, xb, l2w, l2b, 128, 128, t);
    lin4(xb, xa, l3w, l3b, 128,  64, t);
    lin4(xa, xb, l4w, l4b,  64,  64, t);
    lin4(xb, xa, l5w, l5b,  64,  32, t);

    if (t < GPB) {
        float s = l6b[0];
#pragma unroll
        for (int i = 0; i < 32; i++) s += xa[t][i] * __ldg(l6w + i);
        out[g0 + t] = s;
    }
}

// ---------------- launch -----------------------------------------------------
extern "C" void kernel_launch(void* const* d_in, const int* in_sizes, int n_in,
                              void* d_out, int out_size) {
    const float* in_feat = (const float*)d_in[0];
    const float* ev      = (const float*)d_in[1];
    const int*   src     = (const int*)  d_in[2];
    const int*   dst     = (const int*)  d_in[3];
    const int*   gids    = (const int*)  d_in[4];
    const float* c0w1 = (const float*)d_in[5];
    const float* c0b1 = (const float*)d_in[6];
    const float* c0w2 = (const float*)d_in[7];
    const float* c0b2 = (const float*)d_in[8];
    const float* c1w1 = (const float*)d_in[9];
    const float* c1b1 = (const float*)d_in[10];
    const float* c1w2 = (const float*)d_in[11];
    const float* c1b2 = (const float*)d_in[12];
    const float* l0w = (const float*)d_in[13]; const float* l0b = (const float*)d_in[14];
    const float* l1w = (const float*)d_in[15]; const float* l1b = (const float*)d_in[16];
    const float* l2w = (const float*)d_in[17]; const float* l2b = (const float*)d_in[18];
    const float* l3w = (const float*)d_in[19]; const float* l3b = (const float*)d_in[20];
    const float* l4w = (const float*)d_in[21]; const float* l4b = (const float*)d_in[22];
    const float* l5w = (const float*)d_in[23]; const float* l5b = (const float*)d_in[24];
    const float* l6w = (const float*)d_in[25]; const float* l6b = (const float*)d_in[26];
    float* out = (float*)d_out;

    deg_kernel <<<(N_EDGES + 255) / 256, 256>>>(dst);
    offs_kernel<<<(N_NODES + 255) / 256, 256>>>();
    fill_kernel<<<(N_EDGES + 255) / 256, 256>>>(src, dst);

    gather1_kernel<<<(N_NODES * 32 + 255) / 256, 256>>>(in_feat);
    mlp1_kernel<<<(N_NODES + 127) / 128, 128>>>(in_feat, c0w1, c0b1, c0w2, c0b2, gids);

    gather2_kernel<<<(N_NODES * 32 + 255) / 256, 256>>>();
    mlp2_kernel<<<(N_NODES + 127) / 128, 128>>>(c1w1, c1b1, c1w2, c1b2, gids);

    tower_kernel<<<NB / GPB, 256>>>(ev,
                                    l0w, l0b, l1w, l1b, l2w, l2b, l3w, l3b,
                                    l4w, l4b, l5w, l5b, l6w, l6b, out);
}